// round 6
// baseline (speedup 1.0000x reference)
#include <cuda_runtime.h>
#include <cuda_fp16.h>

// GCN 2-layer, CSR-gather formulation:
//   deg[v] = in-edge count ; dinv = rsqrt(deg+1)
//   hs = half((X @ W) * dinv[row])     (f32x2-packed GEMM, fp16 output)
//   out[v] = relu(dinv[v]*(sum_{s->v} hs[s] + hs[v]) + b)   (fp32 accumulate)
// CSR built once, reused by both layers. edge_index is int32.

#define MAXN 100000
#define HID 64
#define NEDGE_MAX 1600000
#define SCAN_B 512

__device__ __half2 g_hsh[MAXN * 32];    // scaled GEMM output, fp16 (12.8 MB)
__device__ float   g_h1 [MAXN * HID];   // layer-1 output, fp32
__device__ float   g_dinv[MAXN];
__device__ int     g_deg [MAXN];
__device__ int     g_rowstart[MAXN + 1];
__device__ int     g_cursor[MAXN];
__device__ int     g_csrc[NEDGE_MAX];
__device__ int     g_bsum[256];

// packed fp32x2 fma: acc += a * b
__device__ __forceinline__ void fma2(float2& acc, const float2& a, const float2& b) {
    unsigned long long* pa = (unsigned long long*)&acc;
    asm("fma.rn.f32x2 %0, %1, %2, %0;"
        : "+l"(*pa)
        : "l"(*(const unsigned long long*)&a), "l"(*(const unsigned long long*)&b));
}

// ---------------------------------------------------------------------------
__global__ void deg_count_kernel(const int* __restrict__ dst, int E) {
    int i = blockIdx.x * blockDim.x + threadIdx.x;
    if (i < E) atomicAdd(&g_deg[dst[i]], 1);
}

// ---- scan part 1: per-block exclusive scan + block sums ---------------------
__global__ void scan1_kernel(int n) {
    __shared__ int sm[SCAN_B];
    int tid = threadIdx.x;
    int i = blockIdx.x * SCAN_B + tid;
    int v = (i < n) ? g_deg[i] : 0;
    sm[tid] = v;
    __syncthreads();
#pragma unroll
    for (int off = 1; off < SCAN_B; off <<= 1) {
        int t = (tid >= off) ? sm[tid - off] : 0;
        __syncthreads();
        sm[tid] += t;
        __syncthreads();
    }
    if (i < n) g_rowstart[i] = sm[tid] - v;
    if (tid == SCAN_B - 1) g_bsum[blockIdx.x] = sm[tid];
}

// ---- scan part 2 (fused): finalize rowstart, cursor, dinv -------------------
__global__ void scan23_kernel(int n, int E, int nb) {
    __shared__ int sb[256];
    int tid = threadIdx.x;
    int v = (tid < nb) ? g_bsum[tid] : 0;
    sb[tid] = v;
    __syncthreads();
#pragma unroll
    for (int off = 1; off < 256; off <<= 1) {
        int t = (tid >= off) ? sb[tid - off] : 0;
        __syncthreads();
        sb[tid] += t;
        __syncthreads();
    }
    int excl = sb[tid] - v;
    __syncthreads();
    sb[tid] = excl;
    __syncthreads();

    int i = blockIdx.x * blockDim.x + tid;
    if (i < n) {
        int r = g_rowstart[i] + sb[i >> 9];
        g_rowstart[i] = r;
        g_cursor[i] = r;
        g_dinv[i] = rsqrtf((float)(g_deg[i] + 1));
    }
    if (i == 0) g_rowstart[n] = E;
}

__global__ void fill_kernel(const int* __restrict__ src,
                            const int* __restrict__ dst, int E) {
    int i = blockIdx.x * blockDim.x + threadIdx.x;
    if (i < E) {
        int pos = atomicAdd(&g_cursor[dst[i]], 1);
        g_csrc[pos] = src[i];
    }
}

// ---------------------------------------------------------------------------
// hs[row] = half((X[row] @ W) * dinv[row])
// Block = 256 thr = 8 warps; warp computes 8 rows; lane owns cols {2l, 2l+1}.
// f32x2 packing over k (even/odd halves). Two W smem arrays keep LDS
// stride-8B conflict-free: WpA = col 2l pairs, WpB = col 2l+1 pairs.
__global__ void gemm_scale_kernel(const float* __restrict__ X,
                                  const float* __restrict__ W,
                                  __half2* __restrict__ outh, int n) {
    __shared__ float2 WpA[32 * 32];      // 8 KB : (W[2k2][2l], W[2k2+1][2l])
    __shared__ float2 WpB[32 * 32];      // 8 KB : col 2l+1
    __shared__ float4 xs[64][16];        // 16 KB
    int tid = threadIdx.x;

#pragma unroll
    for (int i = tid; i < 32 * HID; i += 256) {
        int k2 = i >> 6, c = i & 63;
        float2 p = make_float2(W[(2 * k2) * HID + c], W[(2 * k2 + 1) * HID + c]);
        if (c & 1) WpB[k2 * 32 + (c >> 1)] = p;
        else       WpA[k2 * 32 + (c >> 1)] = p;
    }

    int tile0 = blockIdx.x * 64;
    const float4* X4 = (const float4*)X;
#pragma unroll
    for (int i = tid; i < 64 * 16; i += 256) {
        int r = i >> 4, q = i & 15;
        int row = tile0 + r;
        xs[r][q] = (row < n) ? X4[(size_t)row * 16 + q]
                             : make_float4(0.f, 0.f, 0.f, 0.f);
    }
    __syncthreads();

    int warp = tid >> 5, lane = tid & 31;
    int r0 = warp * 8;

    float2 accA[8], accB[8];   // col 2l / col 2l+1 ; halves = even/odd k
#pragma unroll
    for (int r = 0; r < 8; r++) {
        accA[r] = make_float2(0.f, 0.f);
        accB[r] = make_float2(0.f, 0.f);
    }

#pragma unroll
    for (int q = 0; q < 16; q++) {       // q covers k = 4q..4q+3
        float2 wA0 = WpA[(2 * q) * 32 + lane];
        float2 wB0 = WpB[(2 * q) * 32 + lane];
        float2 wA1 = WpA[(2 * q + 1) * 32 + lane];
        float2 wB1 = WpB[(2 * q + 1) * 32 + lane];
#pragma unroll
        for (int r = 0; r < 8; r++) {
            float4 xv = xs[r0 + r][q];
            float2 x0 = make_float2(xv.x, xv.y);
            float2 x1 = make_float2(xv.z, xv.w);
            fma2(accA[r], x0, wA0);
            fma2(accB[r], x0, wB0);
            fma2(accA[r], x1, wA1);
            fma2(accB[r], x1, wB1);
        }
    }

#pragma unroll
    for (int r = 0; r < 8; r++) {
        int row = tile0 + r0 + r;
        if (row < n) {
            float s = g_dinv[row];
            float cA = (accA[r].x + accA[r].y) * s;
            float cB = (accB[r].x + accB[r].y) * s;
            outh[(size_t)row * 32 + lane] = __floats2half2_rn(cA, cB);
        }
    }
}

// ---------------------------------------------------------------------------
// One warp per node: acc = hs[v] + sum_{j in row} hs[csrc[j]]  (fp32 acc)
// out[v] = relu(dinv[v]*acc + b)   — out cols {2l, 2l+1} per lane
__global__ void gather_kernel(const float* __restrict__ b,
                              float2* __restrict__ out, int n) {
    int w = (blockIdx.x * blockDim.x + threadIdx.x) >> 5;
    int lane = threadIdx.x & 31;
    if (w >= n) return;
    int v = w;
    int beg = g_rowstart[v];
    int end = g_rowstart[v + 1];
    const __half2* hsh = (const __half2*)g_hsh;

    float2 acc = __half22float2(hsh[(size_t)v * 32 + lane]);   // self term
    int j = beg;
    for (; j + 4 <= end; j += 4) {
        int s0 = g_csrc[j], s1 = g_csrc[j + 1];
        int s2 = g_csrc[j + 2], s3 = g_csrc[j + 3];
        float2 a0 = __half22float2(hsh[(size_t)s0 * 32 + lane]);
        float2 a1 = __half22float2(hsh[(size_t)s1 * 32 + lane]);
        float2 a2 = __half22float2(hsh[(size_t)s2 * 32 + lane]);
        float2 a3 = __half22float2(hsh[(size_t)s3 * 32 + lane]);
        acc.x += (a0.x + a1.x) + (a2.x + a3.x);
        acc.y += (a0.y + a1.y) + (a2.y + a3.y);
    }
    for (; j < end; j++) {
        float2 a = __half22float2(hsh[(size_t)g_csrc[j] * 32 + lane]);
        acc.x += a.x; acc.y += a.y;
    }
    float s = g_dinv[v];
    float2 bb = ((const float2*)b)[lane];   // cols {2l, 2l+1}
    float2 r;
    r.x = fmaxf(fmaf(s, acc.x, bb.x), 0.f);
    r.y = fmaxf(fmaf(s, acc.y, bb.y), 0.f);
    out[(size_t)v * 32 + lane] = r;
}

// ---------------------------------------------------------------------------
extern "C" void kernel_launch(void* const* d_in, const int* in_sizes, int n_in,
                              void* d_out, int out_size) {
    const float* x  = (const float*)d_in[0];
    const int*   ei = (const int*)d_in[1];
    const float* W1 = (const float*)d_in[2];
    const float* b1 = (const float*)d_in[3];
    const float* W2 = (const float*)d_in[4];
    const float* b2 = (const float*)d_in[5];

    int n = in_sizes[0] / HID;       // 100000
    int E = in_sizes[1] / 2;         // 1600000
    const int* src = ei;
    const int* dst = ei + E;

    __half2* hsh = nullptr; cudaGetSymbolAddress((void**)&hsh, g_hsh);
    float*   h1  = nullptr; cudaGetSymbolAddress((void**)&h1,  g_h1);
    int*     deg = nullptr; cudaGetSymbolAddress((void**)&deg, g_deg);

    int nb_scan = (n + SCAN_B - 1) / SCAN_B;             // 196 (<=256)
    int gemm_blocks = (n + 63) / 64;                     // 1563
    int gather_blocks = (n * 32 + 255) / 256;            // 12500

    // ---- degree + CSR (shared by both layers) ----
    cudaMemsetAsync(deg, 0, n * sizeof(int));
    deg_count_kernel<<<(E + 255) / 256, 256>>>(dst, E);
    scan1_kernel<<<nb_scan, SCAN_B>>>(n);
    scan23_kernel<<<(n + 255) / 256, 256>>>(n, E, nb_scan);
    fill_kernel<<<(E + 255) / 256, 256>>>(src, dst, E);

    // ---- layer 1 ----
    gemm_scale_kernel<<<gemm_blocks, 256>>>(x, W1, hsh, n);
    gather_kernel<<<gather_blocks, 256>>>(b1, (float2*)h1, n);

    // ---- layer 2 ----
    gemm_scale_kernel<<<gemm_blocks, 256>>>(h1, W2, hsh, n);
    gather_kernel<<<gather_blocks, 256>>>(b2, (float2*)d_out, n);
}

// round 7
// speedup vs baseline: 1.0259x; 1.0259x over previous
#include <cuda_runtime.h>
#include <cuda_fp16.h>

// GCN 2-layer, CSR-gather formulation:
//   deg[v] = in-edge count ; dinv = rsqrt(deg+1)
//   hs = half((X @ W) * dinv[row])     (f32x2-packed GEMM, fp16 output)
//   out[v] = relu(dinv[v]*(sum_{s->v} hs[s] + hs[v]) + b)   (fp32 accumulate)
// CSR built once, reused by both layers. edge_index is int32.
// gemm1 (needs dinv, ready after scan23) overlaps fill on a side stream.

#define MAXN 100000
#define HID 64
#define NEDGE_MAX 1600000
#define SCAN_B 512

__device__ __half2 g_hsh[MAXN * 32];    // scaled GEMM output, fp16 (12.8 MB)
__device__ float   g_h1 [MAXN * HID];   // layer-1 output, fp32
__device__ float   g_dinv[MAXN];
__device__ int     g_deg [MAXN];
__device__ int     g_rowstart[MAXN + 1];
__device__ int     g_cursor[MAXN];
__device__ int     g_csrc[NEDGE_MAX];
__device__ int     g_bsum[256];

// packed fp32x2 fma: acc += a * b
__device__ __forceinline__ void fma2(float2& acc, const float2& a, const float2& b) {
    unsigned long long* pa = (unsigned long long*)&acc;
    asm("fma.rn.f32x2 %0, %1, %2, %0;"
        : "+l"(*pa)
        : "l"(*(const unsigned long long*)&a), "l"(*(const unsigned long long*)&b));
}

// ---------------------------------------------------------------------------
__global__ void deg_count_kernel(const int* __restrict__ dst, int E) {
    int i = blockIdx.x * blockDim.x + threadIdx.x;
    if (i < E) atomicAdd(&g_deg[dst[i]], 1);
}

// ---- scan part 1: per-block exclusive scan + block sums ---------------------
__global__ void scan1_kernel(int n) {
    __shared__ int sm[SCAN_B];
    int tid = threadIdx.x;
    int i = blockIdx.x * SCAN_B + tid;
    int v = (i < n) ? g_deg[i] : 0;
    sm[tid] = v;
    __syncthreads();
#pragma unroll
    for (int off = 1; off < SCAN_B; off <<= 1) {
        int t = (tid >= off) ? sm[tid - off] : 0;
        __syncthreads();
        sm[tid] += t;
        __syncthreads();
    }
    if (i < n) g_rowstart[i] = sm[tid] - v;
    if (tid == SCAN_B - 1) g_bsum[blockIdx.x] = sm[tid];
}

// ---- scan part 2 (fused): finalize rowstart, cursor, dinv -------------------
__global__ void scan23_kernel(int n, int E, int nb) {
    __shared__ int sb[256];
    int tid = threadIdx.x;
    int v = (tid < nb) ? g_bsum[tid] : 0;
    sb[tid] = v;
    __syncthreads();
#pragma unroll
    for (int off = 1; off < 256; off <<= 1) {
        int t = (tid >= off) ? sb[tid - off] : 0;
        __syncthreads();
        sb[tid] += t;
        __syncthreads();
    }
    int excl = sb[tid] - v;
    __syncthreads();
    sb[tid] = excl;
    __syncthreads();

    int i = blockIdx.x * blockDim.x + tid;
    if (i < n) {
        int r = g_rowstart[i] + sb[i >> 9];
        g_rowstart[i] = r;
        g_cursor[i] = r;
        g_dinv[i] = rsqrtf((float)(g_deg[i] + 1));
    }
    if (i == 0) g_rowstart[n] = E;
}

__global__ void fill_kernel(const int* __restrict__ src,
                            const int* __restrict__ dst, int E) {
    int i = blockIdx.x * blockDim.x + threadIdx.x;
    if (i < E) {
        int pos = atomicAdd(&g_cursor[dst[i]], 1);
        g_csrc[pos] = src[i];
    }
}

// ---------------------------------------------------------------------------
// hs[row] = half((X[row] @ W) * dinv[row])
// Block = 256 thr = 8 warps; warp computes 8 rows; lane owns cols {2l, 2l+1}.
__global__ void gemm_scale_kernel(const float* __restrict__ X,
                                  const float* __restrict__ W,
                                  __half2* __restrict__ outh, int n) {
    __shared__ float2 WpA[32 * 32];      // 8 KB : (W[2k2][2l], W[2k2+1][2l])
    __shared__ float2 WpB[32 * 32];      // 8 KB : col 2l+1
    __shared__ float4 xs[64][16];        // 16 KB
    int tid = threadIdx.x;

#pragma unroll
    for (int i = tid; i < 32 * HID; i += 256) {
        int k2 = i >> 6, c = i & 63;
        float2 p = make_float2(W[(2 * k2) * HID + c], W[(2 * k2 + 1) * HID + c]);
        if (c & 1) WpB[k2 * 32 + (c >> 1)] = p;
        else       WpA[k2 * 32 + (c >> 1)] = p;
    }

    int tile0 = blockIdx.x * 64;
    const float4* X4 = (const float4*)X;
#pragma unroll
    for (int i = tid; i < 64 * 16; i += 256) {
        int r = i >> 4, q = i & 15;
        int row = tile0 + r;
        xs[r][q] = (row < n) ? X4[(size_t)row * 16 + q]
                             : make_float4(0.f, 0.f, 0.f, 0.f);
    }
    __syncthreads();

    int warp = tid >> 5, lane = tid & 31;
    int r0 = warp * 8;

    float2 accA[8], accB[8];
#pragma unroll
    for (int r = 0; r < 8; r++) {
        accA[r] = make_float2(0.f, 0.f);
        accB[r] = make_float2(0.f, 0.f);
    }

#pragma unroll
    for (int q = 0; q < 16; q++) {
        float2 wA0 = WpA[(2 * q) * 32 + lane];
        float2 wB0 = WpB[(2 * q) * 32 + lane];
        float2 wA1 = WpA[(2 * q + 1) * 32 + lane];
        float2 wB1 = WpB[(2 * q + 1) * 32 + lane];
#pragma unroll
        for (int r = 0; r < 8; r++) {
            float4 xv = xs[r0 + r][q];
            float2 x0 = make_float2(xv.x, xv.y);
            float2 x1 = make_float2(xv.z, xv.w);
            fma2(accA[r], x0, wA0);
            fma2(accB[r], x0, wB0);
            fma2(accA[r], x1, wA1);
            fma2(accB[r], x1, wB1);
        }
    }

#pragma unroll
    for (int r = 0; r < 8; r++) {
        int row = tile0 + r0 + r;
        if (row < n) {
            float s = g_dinv[row];
            float cA = (accA[r].x + accA[r].y) * s;
            float cB = (accB[r].x + accB[r].y) * s;
            outh[(size_t)row * 32 + lane] = __floats2half2_rn(cA, cB);
        }
    }
}

// ---------------------------------------------------------------------------
// One warp per node, shuffle-broadcast gather:
//   load up to 32 edge indices with ONE coalesced LDG (lane-strided),
//   broadcast via shfl, row loads issued in unroll-8 blocks (MLP 8).
__global__ void gather_kernel(const float* __restrict__ b,
                              float2* __restrict__ out, int n) {
    int w = (blockIdx.x * blockDim.x + threadIdx.x) >> 5;
    int lane = threadIdx.x & 31;
    if (w >= n) return;
    int v = w;
    int beg = g_rowstart[v];
    int end = g_rowstart[v + 1];
    const __half2* hsh = (const __half2*)g_hsh;

    float2 bb = ((const float2*)b)[lane];                       // cols {2l,2l+1}
    float2 acc = __half22float2(hsh[(size_t)v * 32 + lane]);    // self term

    for (int base = beg; base < end; base += 32) {
        int cnt = end - base;
        if (cnt > 32) cnt = 32;
        int idx = (lane < cnt) ? g_csrc[base + lane] : 0;

        int t = 0;
        for (; t + 8 <= cnt; t += 8) {
            int s0 = __shfl_sync(0xffffffff, idx, t + 0);
            int s1 = __shfl_sync(0xffffffff, idx, t + 1);
            int s2 = __shfl_sync(0xffffffff, idx, t + 2);
            int s3 = __shfl_sync(0xffffffff, idx, t + 3);
            int s4 = __shfl_sync(0xffffffff, idx, t + 4);
            int s5 = __shfl_sync(0xffffffff, idx, t + 5);
            int s6 = __shfl_sync(0xffffffff, idx, t + 6);
            int s7 = __shfl_sync(0xffffffff, idx, t + 7);
            float2 a0 = __half22float2(hsh[(size_t)s0 * 32 + lane]);
            float2 a1 = __half22float2(hsh[(size_t)s1 * 32 + lane]);
            float2 a2 = __half22float2(hsh[(size_t)s2 * 32 + lane]);
            float2 a3 = __half22float2(hsh[(size_t)s3 * 32 + lane]);
            float2 a4 = __half22float2(hsh[(size_t)s4 * 32 + lane]);
            float2 a5 = __half22float2(hsh[(size_t)s5 * 32 + lane]);
            float2 a6 = __half22float2(hsh[(size_t)s6 * 32 + lane]);
            float2 a7 = __half22float2(hsh[(size_t)s7 * 32 + lane]);
            acc.x += ((a0.x + a1.x) + (a2.x + a3.x)) + ((a4.x + a5.x) + (a6.x + a7.x));
            acc.y += ((a0.y + a1.y) + (a2.y + a3.y)) + ((a4.y + a5.y) + (a6.y + a7.y));
        }
        for (; t < cnt; t++) {
            int s = __shfl_sync(0xffffffff, idx, t);
            float2 a = __half22float2(hsh[(size_t)s * 32 + lane]);
            acc.x += a.x; acc.y += a.y;
        }
    }

    float s = g_dinv[v];
    float2 r;
    r.x = fmaxf(fmaf(s, acc.x, bb.x), 0.f);
    r.y = fmaxf(fmaf(s, acc.y, bb.y), 0.f);
    out[(size_t)v * 32 + lane] = r;
}

// ---------------------------------------------------------------------------
extern "C" void kernel_launch(void* const* d_in, const int* in_sizes, int n_in,
                              void* d_out, int out_size) {
    const float* x  = (const float*)d_in[0];
    const int*   ei = (const int*)d_in[1];
    const float* W1 = (const float*)d_in[2];
    const float* b1 = (const float*)d_in[3];
    const float* W2 = (const float*)d_in[4];
    const float* b2 = (const float*)d_in[5];

    int n = in_sizes[0] / HID;       // 100000
    int E = in_sizes[1] / 2;         // 1600000
    const int* src = ei;
    const int* dst = ei + E;

    __half2* hsh = nullptr; cudaGetSymbolAddress((void**)&hsh, g_hsh);
    float*   h1  = nullptr; cudaGetSymbolAddress((void**)&h1,  g_h1);
    int*     deg = nullptr; cudaGetSymbolAddress((void**)&deg, g_deg);

    static cudaStream_t s2 = nullptr;
    static cudaEvent_t evScan = nullptr, evG1 = nullptr;
    if (s2 == nullptr) {
        cudaStreamCreateWithFlags(&s2, cudaStreamNonBlocking);
        cudaEventCreateWithFlags(&evScan, cudaEventDisableTiming);
        cudaEventCreateWithFlags(&evG1, cudaEventDisableTiming);
    }

    int nb_scan = (n + SCAN_B - 1) / SCAN_B;             // 196 (<=256)
    int gemm_blocks = (n + 63) / 64;                     // 1563
    int gather_blocks = (n * 32 + 255) / 256;            // 12500

    // ---- degree + scan (main stream) ----
    cudaMemsetAsync(deg, 0, n * sizeof(int));
    deg_count_kernel<<<(E + 255) / 256, 256>>>(dst, E);
    scan1_kernel<<<nb_scan, SCAN_B>>>(n);
    scan23_kernel<<<(n + 255) / 256, 256>>>(n, E, nb_scan);
    cudaEventRecord(evScan, 0);

    // ---- fork: gemm1 (needs dinv only) overlaps fill ----
    cudaStreamWaitEvent(s2, evScan, 0);
    gemm_scale_kernel<<<gemm_blocks, 256, 0, s2>>>(x, W1, hsh, n);
    cudaEventRecord(evG1, s2);

    fill_kernel<<<(E + 255) / 256, 256>>>(src, dst, E);

    // ---- join, layer 1 gather, layer 2 ----
    cudaStreamWaitEvent(0, evG1, 0);
    gather_kernel<<<gather_blocks, 256>>>(b1, (float2*)h1, n);
    gemm_scale_kernel<<<gemm_blocks, 256>>>(h1, W2, hsh, n);
    gather_kernel<<<gather_blocks, 256>>>(b2, (float2*)d_out, n);
}

// round 8
// speedup vs baseline: 1.2815x; 1.2491x over previous
#include <cuda_runtime.h>
#include <cuda_fp16.h>

// GCN 2-layer, CSR-gather formulation, tensor-core GEMM:
//   deg[v] = in-edge count ; dinv = rsqrt(deg+1)
//   hs = half((X @ W) * dinv[row])     (HMMA m16n8k16, fp16 in, fp32 acc)
//   out[v] = relu(dinv[v]*(sum_{s->v} hs[s] + hs[v]) + b)   (fp32 accumulate)
// CSR built once, reused by both layers. edge_index is int32.
// gemm1 overlaps fill on a side stream. h1 stored fp16 (same rounding as
// gemm2's input conversion would apply anyway).

#define MAXN 100000
#define HID 64
#define NEDGE_MAX 1600000
#define SCAN_B 512

__device__ __half2 g_hsh[MAXN * 32];    // scaled GEMM output, fp16
__device__ __half2 g_h1h[MAXN * 32];    // layer-1 output, fp16
__device__ float   g_dinv[MAXN];
__device__ int     g_deg [MAXN];
__device__ int     g_rowstart[MAXN + 1];
__device__ int     g_cursor[MAXN];
__device__ int     g_csrc[NEDGE_MAX];
__device__ int     g_bsum[256];

// ---------------------------------------------------------------------------
__global__ void deg_count_kernel(const int* __restrict__ dst, int E) {
    int i = blockIdx.x * blockDim.x + threadIdx.x;
    if (i < E) atomicAdd(&g_deg[dst[i]], 1);
}

__global__ void scan1_kernel(int n) {
    __shared__ int sm[SCAN_B];
    int tid = threadIdx.x;
    int i = blockIdx.x * SCAN_B + tid;
    int v = (i < n) ? g_deg[i] : 0;
    sm[tid] = v;
    __syncthreads();
#pragma unroll
    for (int off = 1; off < SCAN_B; off <<= 1) {
        int t = (tid >= off) ? sm[tid - off] : 0;
        __syncthreads();
        sm[tid] += t;
        __syncthreads();
    }
    if (i < n) g_rowstart[i] = sm[tid] - v;
    if (tid == SCAN_B - 1) g_bsum[blockIdx.x] = sm[tid];
}

__global__ void scan23_kernel(int n, int E, int nb) {
    __shared__ int sb[256];
    int tid = threadIdx.x;
    int v = (tid < nb) ? g_bsum[tid] : 0;
    sb[tid] = v;
    __syncthreads();
#pragma unroll
    for (int off = 1; off < 256; off <<= 1) {
        int t = (tid >= off) ? sb[tid - off] : 0;
        __syncthreads();
        sb[tid] += t;
        __syncthreads();
    }
    int excl = sb[tid] - v;
    __syncthreads();
    sb[tid] = excl;
    __syncthreads();

    int i = blockIdx.x * blockDim.x + tid;
    if (i < n) {
        int r = g_rowstart[i] + sb[i >> 9];
        g_rowstart[i] = r;
        g_cursor[i] = r;
        g_dinv[i] = rsqrtf((float)(g_deg[i] + 1));
    }
    if (i == 0) g_rowstart[n] = E;
}

__global__ void fill_kernel(const int* __restrict__ src,
                            const int* __restrict__ dst, int E) {
    int i = blockIdx.x * blockDim.x + threadIdx.x;
    if (i < E) {
        int pos = atomicAdd(&g_cursor[dst[i]], 1);
        g_csrc[pos] = src[i];
    }
}

// ---------------------------------------------------------------------------
// MMA helpers
__device__ __forceinline__ void ldmA(unsigned* a, unsigned addr) {
    asm volatile("ldmatrix.sync.aligned.m8n8.x4.shared.b16 {%0,%1,%2,%3}, [%4];"
                 : "=r"(a[0]), "=r"(a[1]), "=r"(a[2]), "=r"(a[3]) : "r"(addr));
}
__device__ __forceinline__ void ldmB(unsigned* b, unsigned addr) {
    asm volatile("ldmatrix.sync.aligned.m8n8.x2.trans.shared.b16 {%0,%1}, [%2];"
                 : "=r"(b[0]), "=r"(b[1]) : "r"(addr));
}
__device__ __forceinline__ void mma16816(float* c, const unsigned* a, const unsigned* b) {
    asm volatile(
        "mma.sync.aligned.m16n8k16.row.col.f32.f16.f16.f32 "
        "{%0,%1,%2,%3}, {%4,%5,%6,%7}, {%8,%9}, {%0,%1,%2,%3};"
        : "+f"(c[0]), "+f"(c[1]), "+f"(c[2]), "+f"(c[3])
        : "r"(a[0]), "r"(a[1]), "r"(a[2]), "r"(a[3]), "r"(b[0]), "r"(b[1]));
}

// hs[row] = half((X[row] @ W) * dinv[row])
// Block = 256 thr = 8 warps; block tile 128 rows; warp strip = 16 rows x 64 cols.
// FP16IN: X already fp16 (layer 2); else fp32 converted on load.
template <bool FP16IN>
__global__ void gemm_mma_kernel(const void* __restrict__ Xin,
                                const float* __restrict__ W,
                                __half2* __restrict__ outh, int n) {
    __shared__ alignas(16) __half Xh[128][72];
    __shared__ alignas(16) __half Wh[64][72];
    int tid = threadIdx.x;

    // stage W (64x64 fp32 -> fp16)
#pragma unroll
    for (int i = tid; i < 2048; i += 256) {
        int k = (i * 2) >> 6, c = (i * 2) & 63;
        float2 w2 = ((const float2*)W)[i];
        *(__half2*)&Wh[k][c] = __floats2half2_rn(w2.x, w2.y);
    }

    int tile0 = blockIdx.x * 128;
    if constexpr (!FP16IN) {
        const float4* X4 = (const float4*)Xin;
#pragma unroll
        for (int i = tid; i < 128 * 16; i += 256) {
            int r = i >> 4, c4 = i & 15;
            int row = tile0 + r;
            if (row < n) {
                float4 v = X4[(size_t)row * 16 + c4];
                __half2* p = (__half2*)&Xh[r][c4 * 4];
                p[0] = __floats2half2_rn(v.x, v.y);
                p[1] = __floats2half2_rn(v.z, v.w);
            }
        }
    } else {
        const uint2* X2 = (const uint2*)Xin;
#pragma unroll
        for (int i = tid; i < 128 * 16; i += 256) {
            int r = i >> 4, c4 = i & 15;
            int row = tile0 + r;
            if (row < n) *(uint2*)&Xh[r][c4 * 4] = X2[(size_t)row * 16 + c4];
        }
    }
    __syncthreads();

    int warp = tid >> 5, lane = tid & 31;
    int r0 = warp * 16;
    int row0 = tile0 + r0;
    if (row0 >= n) return;          // strips are 16-aligned; n % 16 == 0

    float c[8][4];
#pragma unroll
    for (int nt = 0; nt < 8; nt++)
#pragma unroll
        for (int j = 0; j < 4; j++) c[nt][j] = 0.f;

#pragma unroll
    for (int k0 = 0; k0 < 64; k0 += 16) {
        unsigned a[4];
        unsigned aAddr = (unsigned)__cvta_generic_to_shared(
            &Xh[r0 + (lane & 15)][k0 + ((lane >> 4) << 3)]);
        ldmA(a, aAddr);
        unsigned bAddr = (unsigned)__cvta_generic_to_shared(
            &Wh[k0 + (lane & 15)][0]);
#pragma unroll
        for (int nt = 0; nt < 8; nt++) {
            unsigned bf[2];
            ldmB(bf, bAddr + nt * 16);
            mma16816(c[nt], a, bf);
        }
    }

    int rowA = row0 + (lane >> 2);
    int rowB = rowA + 8;
    float sA = g_dinv[rowA];
    float sB = g_dinv[rowB];
#pragma unroll
    for (int nt = 0; nt < 8; nt++) {
        int h2 = nt * 4 + (lane & 3);
        outh[(size_t)rowA * 32 + h2] = __floats2half2_rn(c[nt][0] * sA, c[nt][1] * sA);
        outh[(size_t)rowB * 32 + h2] = __floats2half2_rn(c[nt][2] * sB, c[nt][3] * sB);
    }
}

// ---------------------------------------------------------------------------
// One warp per node, shuffle-broadcast gather (fp32 accumulate).
// FP16OUT: write half2 (layer 1) vs float2 (final output).
template <bool FP16OUT>
__global__ void gather_kernel(const float* __restrict__ b,
                              void* __restrict__ outv, int n) {
    int w = (blockIdx.x * blockDim.x + threadIdx.x) >> 5;
    int lane = threadIdx.x & 31;
    if (w >= n) return;
    int v = w;
    int beg = g_rowstart[v];
    int end = g_rowstart[v + 1];
    const __half2* hsh = (const __half2*)g_hsh;

    float2 bb = ((const float2*)b)[lane];
    float2 acc = __half22float2(hsh[(size_t)v * 32 + lane]);   // self term

    for (int base = beg; base < end; base += 32) {
        int cnt = end - base;
        if (cnt > 32) cnt = 32;
        int idx = (lane < cnt) ? g_csrc[base + lane] : 0;

        int t = 0;
        for (; t + 8 <= cnt; t += 8) {
            int s0 = __shfl_sync(0xffffffff, idx, t + 0);
            int s1 = __shfl_sync(0xffffffff, idx, t + 1);
            int s2 = __shfl_sync(0xffffffff, idx, t + 2);
            int s3 = __shfl_sync(0xffffffff, idx, t + 3);
            int s4 = __shfl_sync(0xffffffff, idx, t + 4);
            int s5 = __shfl_sync(0xffffffff, idx, t + 5);
            int s6 = __shfl_sync(0xffffffff, idx, t + 6);
            int s7 = __shfl_sync(0xffffffff, idx, t + 7);
            float2 a0 = __half22float2(hsh[(size_t)s0 * 32 + lane]);
            float2 a1 = __half22float2(hsh[(size_t)s1 * 32 + lane]);
            float2 a2 = __half22float2(hsh[(size_t)s2 * 32 + lane]);
            float2 a3 = __half22float2(hsh[(size_t)s3 * 32 + lane]);
            float2 a4 = __half22float2(hsh[(size_t)s4 * 32 + lane]);
            float2 a5 = __half22float2(hsh[(size_t)s5 * 32 + lane]);
            float2 a6 = __half22float2(hsh[(size_t)s6 * 32 + lane]);
            float2 a7 = __half22float2(hsh[(size_t)s7 * 32 + lane]);
            acc.x += ((a0.x + a1.x) + (a2.x + a3.x)) + ((a4.x + a5.x) + (a6.x + a7.x));
            acc.y += ((a0.y + a1.y) + (a2.y + a3.y)) + ((a4.y + a5.y) + (a6.y + a7.y));
        }
        for (; t < cnt; t++) {
            int s = __shfl_sync(0xffffffff, idx, t);
            float2 a = __half22float2(hsh[(size_t)s * 32 + lane]);
            acc.x += a.x; acc.y += a.y;
        }
    }

    float s = g_dinv[v];
    float rx = fmaxf(fmaf(s, acc.x, bb.x), 0.f);
    float ry = fmaxf(fmaf(s, acc.y, bb.y), 0.f);
    if constexpr (FP16OUT) {
        ((__half2*)outv)[(size_t)v * 32 + lane] = __floats2half2_rn(rx, ry);
    } else {
        ((float2*)outv)[(size_t)v * 32 + lane] = make_float2(rx, ry);
    }
}

// ---------------------------------------------------------------------------
extern "C" void kernel_launch(void* const* d_in, const int* in_sizes, int n_in,
                              void* d_out, int out_size) {
    const float* x  = (const float*)d_in[0];
    const int*   ei = (const int*)d_in[1];
    const float* W1 = (const float*)d_in[2];
    const float* b1 = (const float*)d_in[3];
    const float* W2 = (const float*)d_in[4];
    const float* b2 = (const float*)d_in[5];

    int n = in_sizes[0] / HID;       // 100000
    int E = in_sizes[1] / 2;         // 1600000
    const int* src = ei;
    const int* dst = ei + E;

    __half2* hsh = nullptr; cudaGetSymbolAddress((void**)&hsh, g_hsh);
    __half2* h1h = nullptr; cudaGetSymbolAddress((void**)&h1h, g_h1h);
    int*     deg = nullptr; cudaGetSymbolAddress((void**)&deg, g_deg);

    static cudaStream_t s2 = nullptr;
    static cudaEvent_t evScan = nullptr, evG1 = nullptr;
    if (s2 == nullptr) {
        cudaStreamCreateWithFlags(&s2, cudaStreamNonBlocking);
        cudaEventCreateWithFlags(&evScan, cudaEventDisableTiming);
        cudaEventCreateWithFlags(&evG1, cudaEventDisableTiming);
    }

    int nb_scan = (n + SCAN_B - 1) / SCAN_B;             // 196 (<=256)
    int gemm_blocks = (n + 127) / 128;                   // 782
    int gather_blocks = (n * 32 + 255) / 256;            // 12500

    // ---- degree + scan (main stream) ----
    cudaMemsetAsync(deg, 0, n * sizeof(int));
    deg_count_kernel<<<(E + 255) / 256, 256>>>(dst, E);
    scan1_kernel<<<nb_scan, SCAN_B>>>(n);
    scan23_kernel<<<(n + 255) / 256, 256>>>(n, E, nb_scan);
    cudaEventRecord(evScan, 0);

    // ---- fork: gemm1 (needs dinv only) overlaps fill ----
    cudaStreamWaitEvent(s2, evScan, 0);
    gemm_mma_kernel<false><<<gemm_blocks, 256, 0, s2>>>(x, W1, hsh, n);
    cudaEventRecord(evG1, s2);

    fill_kernel<<<(E + 255) / 256, 256>>>(src, dst, E);

    // ---- join, layer 1 gather (fp16 out), layer 2 ----
    cudaStreamWaitEvent(0, evG1, 0);
    gather_kernel<true><<<gather_blocks, 256>>>(b1, h1h, n);
    gemm_mma_kernel<true><<<gemm_blocks, 256>>>(h1h, W2, hsh, n);
    gather_kernel<false><<<gather_blocks, 256>>>(b2, d_out, n);
}